// round 17
// baseline (speedup 1.0000x reference)
#include <cuda_runtime.h>

// SofaNetEllipse via Chebyshev spectral compression (NQ=16) — two kernels.
//
// Kernel A: exact MLP (VALUE ONLY — no JVP chains) at 16 Chebyshev nodes,
//           2 threads/node, TPBA=32. The tangent q = dp/dalpha is obtained by
//           ANALYTIC Chebyshev differentiation of the p-series
//           (d_{k-1} = d_{k+1} + 2k c_k, d_0 halved, x INVXH chain rule),
//           halving A's layer-1 FLOPs and register pressure.
// Kernel B: R12's proven eval kernel (38 regs): Clenshaw on the 4 series.

#define NAB   1024
#define NCOL  2049
#define HALF  1025
#define H     64
#define TPBA  32      // kernel A: one warp, 2 threads/node x 16 nodes
#define TPB2  256     // kernel B
#define NQ    16      // Chebyshev nodes / coefficients

#define XH    0.7853981633974483f   // pi/4  (half-width of [0, pi/2])
#define INVXH 1.2732395447351628f   // 4/pi  (s = alpha*INVXH - 1)

typedef unsigned long long u64;

__device__ __align__(16) float4 g_coef[NAB * NQ];   // 256 KB scratch

__device__ __forceinline__ float fast_tanh(float x) {
    // tanh(x) = 1 - 2/(exp(2x)+1); abs err ~1e-6, saturates correctly.
    float e = __expf(x + x);
    return 1.0f - __fdividef(2.0f, e + 1.0f);
}

__device__ __forceinline__ u64 fma2(u64 a, u64 b, u64 c) {
    u64 d;
    asm("fma.rn.f32x2 %0, %1, %2, %3;" : "=l"(d) : "l"(a), "l"(b), "l"(c));
    return d;
}
__device__ __forceinline__ u64 pack2(float lo, float hi) {
    u64 r;
    asm("mov.b64 %0, {%1, %2};" : "=l"(r) : "f"(lo), "f"(hi));
    return r;
}
__device__ __forceinline__ float2 unpack2(u64 v) {
    float2 r;
    asm("mov.b64 {%0, %1}, %2;" : "=f"(r.x), "=f"(r.y) : "l"(v));
    return r;
}

// ======================= Kernel A: coefficients =======================
__global__ __launch_bounds__(TPBA)
void sofanet_coef_kernel(const float* __restrict__ w0,
                         const float* __restrict__ w1,
                         const float* __restrict__ w2,
                         const float* __restrict__ b0,
                         const float* __restrict__ b1,
                         const float* __restrict__ b2)
{
    const int n   = blockIdx.x;   // network id
    const int tid = threadIdx.x;  // 0..31

    __shared__ __align__(16) float  w1s[H * H];   // 16 KB
    __shared__ float w0s[H], b0s[H], b1s[H];
    __shared__ float w2s[2 * H];
    __shared__ float b2s[2];
    __shared__ float2 nodes2[NQ];   // p(x_q) = (p0, p1)
    __shared__ float2 cser[NQ];     // Chebyshev coeffs of (p0, p1)
    __shared__ float2 dser[NQ];     // derivative coeffs (scaled by INVXH)

    // ---- stage weights (32 threads) ----
    {
        const float4* src = reinterpret_cast<const float4*>(w1 + (size_t)n * H * H);
        float4* dst = reinterpret_cast<float4*>(w1s);
        #pragma unroll
        for (int i = tid; i < (H * H) / 4; i += TPBA) dst[i] = src[i];

        w0s[tid]      = w0[(size_t)n * H + tid];
        w0s[tid + 32] = w0[(size_t)n * H + tid + 32];
        b0s[tid]      = b0[(size_t)n * H + tid];
        b0s[tid + 32] = b0[(size_t)n * H + tid + 32];
        b1s[tid]      = b1[(size_t)n * H + tid];
        b1s[tid + 32] = b1[(size_t)n * H + tid + 32];
        #pragma unroll
        for (int r = 0; r < 4; ++r)
            w2s[tid + 32 * r] = w2[(size_t)n * 2 * H + tid + 32 * r];
        if (tid < 2) b2s[tid] = b2[(size_t)n * 2 + tid];
    }
    __syncthreads();

    // ---- exact MLP (value only) at 16 Chebyshev nodes (2 threads/node) ----
    {
        const int q    = tid >> 1;        // node 0..15
        const int half = tid & 1;         // row half
        const float theta = (2 * q + 1) * (3.14159265358979323846f / (2.0f * NQ));
        const float xq = XH * (1.0f + cosf(theta));   // node in [0, pi/2]

        float h1[H];
        #pragma unroll
        for (int j = 0; j < H; ++j)
            h1[j] = fast_tanh(fmaf(w0s[j], xq, b0s[j]));

        float p0 = 0.f, p1 = 0.f;
        const int i0 = half * 32;
        #pragma unroll 2
        for (int i = i0; i < i0 + 32; ++i) {
            float u = b1s[i];
            const float* ra = &w1s[i * H];
            #pragma unroll
            for (int j = 0; j < H; j += 4) {
                const float4 wa = *reinterpret_cast<const float4*>(ra + j);
                u = fmaf(wa.x, h1[j    ], u);
                u = fmaf(wa.y, h1[j + 1], u);
                u = fmaf(wa.z, h1[j + 2], u);
                u = fmaf(wa.w, h1[j + 3], u);
            }
            const float th = fast_tanh(u);
            p0 = fmaf(w2s[i    ], th, p0);
            p1 = fmaf(w2s[H + i], th, p1);
        }

        // combine the two halves (adjacent lanes, same warp, all lanes active)
        p0 += __shfl_xor_sync(0xFFFFFFFFu, p0, 1);
        p1 += __shfl_xor_sync(0xFFFFFFFFu, p1, 1);

        if (half == 0)
            nodes2[q] = make_float2(p0 + b2s[0], p1 + b2s[1]);
    }
    __syncwarp();

    // ---- DCT -> p-series coefficients (threads 0..15) ----
    if (tid < NQ) {
        const int k = tid;
        float s0 = 0.f, s1 = 0.f;
        #pragma unroll
        for (int q = 0; q < NQ; ++q) {
            const int m = (k * (2 * q + 1)) & (4 * NQ - 1);   // angle mod 2*pi
            const float c = __cosf((float)m * (3.14159265358979323846f / (2.0f * NQ)));
            const float2 f = nodes2[q];
            s0 = fmaf(c, f.x, s0);
            s1 = fmaf(c, f.y, s1);
        }
        const float sc = (k == 0) ? (1.0f / NQ) : (2.0f / NQ);
        cser[k] = make_float2(s0 * sc, s1 * sc);
    }
    __syncwarp();

    // ---- analytic derivative coefficients (thread 0; serial 16-step) ----
    // d_{NQ-1} = 0; for k = NQ-1..1:  d_{k-1} = d_{k+1} + 2k c_k; d_0 *= 1/2.
    // Chain rule: q(alpha) = p'(s) * INVXH.
    if (tid == 0) {
        float dx2 = 0.f, dy2 = 0.f;       // d_{k+1}
        float dx1 = 0.f, dy1 = 0.f;       // d_k being produced (init d_{NQ-1}=0)
        dser[NQ - 1] = make_float2(0.f, 0.f);
        #pragma unroll
        for (int k = NQ - 1; k >= 1; --k) {
            // d_{k-1} = d_{k+1} + 2k * c_k
            const float2 c = cser[k];
            float nx = dx2 + 2.0f * (float)k * c.x;
            float ny = dy2 + 2.0f * (float)k * c.y;
            if (k == 1) { nx *= 0.5f; ny *= 0.5f; }   // halve d_0
            dser[k - 1] = make_float2(nx * INVXH, ny * INVXH);
            dx2 = dx1;  dy2 = dy1;        // shift: old d_k becomes d_{k+1}
            dx1 = nx;   dy1 = ny;
        }
        // fix scaling of dser[NQ-1] (zero, already fine) and re-store raw:
        // note dser[k-1] stored already includes INVXH; d_0 halving applied.
    }
    __syncwarp();

    // ---- pack and store ----
    if (tid < NQ) {
        const float2 c = cser[tid];
        const float2 d = dser[tid];
        g_coef[n * NQ + tid] = make_float4(c.x, c.y, d.x, d.y);
    }
}

// ======================= Kernel B: evaluation (R12 form) =======================
__global__ __launch_bounds__(TPB2, 6)
void sofanet_eval_kernel(const float* __restrict__ alpha,
                         float* __restrict__ out)
{
    const int n   = blockIdx.x;   // network id
    const int tid = threadIdx.x;

    __shared__ __align__(16) float4 coef[NQ];   // 256 B
    __shared__ float xlast_s;

    // stage coefficients (64 floats, coalesced)
    if (tid < NQ * 4) {
        const float* src = (const float*)(g_coef + (size_t)n * NQ);
        ((float*)coef)[tid] = src[tid];
    }
    __syncthreads();

    const size_t AR  = (size_t)NAB * NCOL;
    const size_t row = (size_t)n * NCOL;
    float xlast = 0.0f;
    (void)xlast;

    const u64 NEG1 = pack2(-1.0f, -1.0f);

    // 5 strided tiles cover m = 0..1024 (TPB2=256); remap so m=0 -> t=1024.
    for (int k = 0; k < 5; ++k) {
        const int m = k * TPB2 + tid;
        const bool active = (m < HALF);
        int t = 0;
        if (active) { t = m + (HALF - 1); if (t >= HALF) t -= HALF; }  // bijection

        float xp = 0.f, yp = 0.f, xpp = 0.f, ypp = 0.f;

        if (active) {
            const float x = alpha[t];
            const float s = fmaf(x, INVXH, -1.0f);
            const float twos = s + s;
            const u64 TWOS = pack2(twos, twos);

            // Clenshaw (packed): b_k = c_k - b_{k+2} + 2s*b_{k+1}
            u64 bAx = 0ull, bAz = 0ull;   // b_{k+1}: (x,y) and (z,w) lanes
            u64 bBx = 0ull, bBz = 0ull;   // b_{k+2}
            const ulonglong2* cp = reinterpret_cast<const ulonglong2*>(coef);
            #pragma unroll
            for (int kk = NQ - 1; kk >= 1; --kk) {
                const ulonglong2 c = cp[kk];
                const u64 nx = fma2(TWOS, bAx, fma2(bBx, NEG1, c.x));
                const u64 nz = fma2(TWOS, bAz, fma2(bBz, NEG1, c.y));
                bBx = bAx;  bBz = bAz;
                bAx = nx;   bAz = nz;
            }
            const float4 c0 = coef[0];
            const float2 aX = unpack2(bAx), aZ = unpack2(bAz);
            const float2 bX = unpack2(bBx), bZ = unpack2(bBz);
            const float p0 = fmaf(s, aX.x, c0.x - bX.x);
            const float p1 = fmaf(s, aX.y, c0.y - bX.y);
            const float q0 = fmaf(s, aZ.x, c0.z - bZ.x);
            const float q1 = fmaf(s, aZ.y, c0.w - bZ.y);

            // square + JVP of square
            const float a  = p0 * p0;
            const float b  = p1 * p1;
            const float da = 2.0f * p0 * q0;
            const float db = 2.0f * p1 * q1;

            // trig epilogue (cos(x)-1 = -2*sin^2(x/2), cancellation-free)
            const float s2v = __sinf(0.5f * x);
            const float cm1 = -2.0f * s2v * s2v;
            const float sa  = __sinf(x);
            const float ca  = 1.0f + cm1;

            xp  = a * cm1;
            yp  = b * sa;
            xpp = fmaf(da, cm1, -a * sa);
            ypp = fmaf(db, sa,  b * ca);

            out[           row + t] = xp;
            out[AR       + row + t] = yp;
            out[2 * AR   + row + t] = xpp;
            out[3 * AR   + row + t] = ypp;

            if (t == HALF - 1) xlast_s = xp;   // only (k=0, tid=0)
        }

        if (k == 0) {            // uniform branch: all threads participate
            __syncthreads();
            xlast = xlast_s;
        }

        // mirror writes: dest col 2048 - t for t in 0..1023
        if (active && t < HALF - 1) {
            const int c2 = (NCOL - 1) - t;
            out[           row + c2] = 2.0f * xlast - xp;
            out[AR       + row + c2] = yp;
            out[2 * AR   + row + c2] = xpp;
            out[3 * AR   + row + c2] = -ypp;
        }
    }
}

extern "C" void kernel_launch(void* const* d_in, const int* in_sizes, int n_in,
                              void* d_out, int out_size)
{
    const float* alpha = (const float*)d_in[0];
    const float* w0    = (const float*)d_in[1];
    const float* w1    = (const float*)d_in[2];
    const float* w2    = (const float*)d_in[3];
    const float* b0    = (const float*)d_in[4];
    const float* b1    = (const float*)d_in[5];
    const float* b2    = (const float*)d_in[6];
    float* out = (float*)d_out;

    sofanet_coef_kernel<<<NAB, TPBA>>>(w0, w1, w2, b0, b1, b2);
    sofanet_eval_kernel<<<NAB, TPB2>>>(alpha, out);
}